// round 16
// baseline (speedup 1.0000x reference)
#include <cuda_runtime.h>
#include <cuda_bf16.h>
#include <cstdint>

#define NN 100000      // nodes
#define EE 1600000     // edges
#define PP 100000      // pairs (each of pos/neg)
#define DH 128
#define DMLP 512
#define DPRED 64
#define LAYERS 3
#define SCAN_B 1024
#define SCAN_NB ((NN + SCAN_B - 1) / SCAN_B)   // 98

// ---------------- scratch (static device allocations) ----------------
__device__ float g_h[(size_t)NN * DH];                   // fp32 h between layers
__device__ float g_z[(size_t)NN * DMLP];                 // aliased: zh/zl bf16, or Vhi/Vlo
__device__ __nv_bfloat16 g_w1h[LAYERS * DMLP * DH], g_w1l[LAYERS * DMLP * DH];
__device__ __nv_bfloat16 g_w2h[LAYERS * DH * DMLP], g_w2l[LAYERS * DH * DMLP];
__device__ __nv_bfloat16 g_wp1h[DPRED * DH], g_wp1l[DPRED * DH];
// CSR scratch
__device__ int g_deg[NN];
__device__ int g_incl[NN];
__device__ int g_off[NN];
__device__ int g_cur[NN];
__device__ int g_bsum[128];
__device__ int g_csr[EE];

static inline int cdiv(int a, int b) { return (a + b - 1) / b; }

// ---------------- common helpers ----------------
__device__ __forceinline__ uint32_t swz64(uint32_t off) { return off ^ ((off >> 3) & 0x30u); }

__device__ __forceinline__ void cpasync16(uint32_t dst, const void* src, bool pred) {
    asm volatile("cp.async.cg.shared.global [%0], [%1], 16, %2;"
                 :: "r"(dst), "l"(src), "r"(pred ? 16 : 0) : "memory");
}
__device__ __forceinline__ void cp_commit() {
    asm volatile("cp.async.commit_group;" ::: "memory");
}
template<int N> __device__ __forceinline__ void cp_wait() {
    asm volatile("cp.async.wait_group %0;" :: "n"(N) : "memory");
}

__device__ __forceinline__ void split2(float a, float b, uint32_t& hi, uint32_t& lo) {
    __nv_bfloat16 ha = __float2bfloat16(a), hb = __float2bfloat16(b);
    __nv_bfloat16 la = __float2bfloat16(a - __bfloat162float(ha));
    __nv_bfloat16 lb = __float2bfloat16(b - __bfloat162float(hb));
    __nv_bfloat162 h = __halves2bfloat162(ha, hb), l = __halves2bfloat162(la, lb);
    hi = *reinterpret_cast<uint32_t*>(&h);
    lo = *reinterpret_cast<uint32_t*>(&l);
}

__device__ __forceinline__ void mma_bf16(float* c, const uint32_t* a, const uint32_t* b) {
    asm volatile("mma.sync.aligned.m16n8k16.row.col.f32.bf16.bf16.f32 "
                 "{%0,%1,%2,%3}, {%4,%5,%6,%7}, {%8,%9}, {%0,%1,%2,%3};"
                 : "+f"(c[0]), "+f"(c[1]), "+f"(c[2]), "+f"(c[3])
                 : "r"(a[0]), "r"(a[1]), "r"(a[2]), "r"(a[3]), "r"(b[0]), "r"(b[1]));
}
__device__ __forceinline__ void ldsm4(uint32_t addr, uint32_t* r) {
    asm volatile("ldmatrix.sync.aligned.m8n8.x4.shared.b16 {%0,%1,%2,%3}, [%4];"
                 : "=r"(r[0]), "=r"(r[1]), "=r"(r[2]), "=r"(r[3]) : "r"(addr));
}

// ---------------- CSR build kernels ----------------
__global__ void zero_int_kernel(int* __restrict__ p, int n) {
    int i = blockIdx.x * blockDim.x + threadIdx.x;
    if (i < n) p[i] = 0;
}
__global__ void hist_kernel(const int* __restrict__ dst, int* __restrict__ deg, int E) {
    int e = blockIdx.x * blockDim.x + threadIdx.x;
    if (e < E) atomicAdd(&deg[__ldg(dst + e)], 1);
}
__global__ void scan_block_kernel(const int* __restrict__ deg, int* __restrict__ incl,
                                  int* __restrict__ bsum, int n) {
    __shared__ int sm[SCAN_B];
    int i = blockIdx.x * SCAN_B + threadIdx.x;
    int v = (i < n) ? deg[i] : 0;
    sm[threadIdx.x] = v;
    __syncthreads();
    for (int o = 1; o < SCAN_B; o <<= 1) {
        int t = (threadIdx.x >= o) ? sm[threadIdx.x - o] : 0;
        __syncthreads();
        sm[threadIdx.x] += t;
        __syncthreads();
    }
    if (i < n) incl[i] = sm[threadIdx.x];
    if (threadIdx.x == SCAN_B - 1) bsum[blockIdx.x] = sm[SCAN_B - 1];
}
__global__ void scan_sums_kernel(int* __restrict__ bsum, int nb) {
    __shared__ int sm[128];
    int v = (threadIdx.x < nb) ? bsum[threadIdx.x] : 0;
    sm[threadIdx.x] = v;
    __syncthreads();
    for (int o = 1; o < 128; o <<= 1) {
        int t = (threadIdx.x >= o) ? sm[threadIdx.x - o] : 0;
        __syncthreads();
        sm[threadIdx.x] += t;
        __syncthreads();
    }
    if (threadIdx.x < nb) bsum[threadIdx.x] = sm[threadIdx.x] - v;   // exclusive
}
__global__ void finalize_off_kernel(const int* __restrict__ incl, const int* __restrict__ deg,
                                    const int* __restrict__ bsum,
                                    int* __restrict__ off, int* __restrict__ cur, int n) {
    int i = blockIdx.x * blockDim.x + threadIdx.x;
    if (i >= n) return;
    int o = incl[i] - deg[i] + bsum[i / SCAN_B];
    off[i] = o;
    cur[i] = o;
}
__global__ void fill_kernel(const int* __restrict__ src, const int* __restrict__ dst,
                            int* __restrict__ cur, int* __restrict__ csr, int E) {
    int e = blockIdx.x * blockDim.x + threadIdx.x;
    if (e >= E) return;
    int p = atomicAdd(&cur[__ldg(dst + e)], 1);
    csr[p] = __ldg(src + e);
}

// in[b][R][C] fp32 -> outh/outl [b][C][R] bf16 (transpose + split); R,C multiples of 32
__global__ void transpose_split_kernel(const float* __restrict__ in,
                                       __nv_bfloat16* __restrict__ outh,
                                       __nv_bfloat16* __restrict__ outl, int R, int C) {
    __shared__ float tile[32][33];
    const float* ib = in + (size_t)blockIdx.z * R * C;
    int r = blockIdx.y * 32 + threadIdx.y;
    int c = blockIdx.x * 32 + threadIdx.x;
    tile[threadIdx.y][threadIdx.x] = ib[(size_t)r * C + c];
    __syncthreads();
    int ro = blockIdx.x * 32 + threadIdx.y;
    int co = blockIdx.y * 32 + threadIdx.x;
    float v = tile[threadIdx.x][threadIdx.y];
    __nv_bfloat16 h = __float2bfloat16(v);
    __nv_bfloat16 l = __float2bfloat16(v - __bfloat162float(h));
    size_t o = (size_t)blockIdx.z * R * C + (size_t)ro * R + co;
    outh[o] = h;
    outl[o] = l;
}

// ================ FUSED gather + GEMM1 (warp-specialized) ================
// z[M,512] = relu((h+agg) @ W1 + b1), gather fused as producer warps.
// 384 threads: warps 0-7 MMA (256 thr), warps 8-11 producers (128 thr).
// SMEM: A persistent 64KB (4 K-chunks x [hi 8KB | lo 8KB]), B 3 stages x 16KB at 64KB.
// Producers signal chunk k via bar.arrive(1+k, 384); consumers bar.sync(1+k, 384) once.
// B pipeline sync uses bar.sync(5, 256) (consumers only).
#define FG1_SMEM (65536 + 3 * 16384)

__global__ void __launch_bounds__(384, 1)
fused_gemm1(const float* __restrict__ H,
            const int* __restrict__ off, const int* __restrict__ deg,
            const int* __restrict__ csr,
            const __nv_bfloat16* __restrict__ Bhi, const __nv_bfloat16* __restrict__ Blo,
            const float* __restrict__ bias,
            __nv_bfloat16* __restrict__ Chi, __nv_bfloat16* __restrict__ Clo,
            int M) {
    extern __shared__ char smem[];
    const uint32_t sbase = (uint32_t)__cvta_generic_to_shared(smem);
    const int tid = threadIdx.x;
    const int row0 = blockIdx.x * 128;

    if (tid >= 256) {
        // ---------------- producer warps: gather + split into A smem ----------------
        int ptid = tid - 256;           // 0..127
        int pwarp = ptid >> 5;          // 0..3
        int plane = ptid & 31;
        int half = plane >> 4;          // two nodes per warp iteration
        int hl = plane & 15;            // 16 lanes per node, float2 per lane
#pragma unroll
        for (int k = 0; k < 4; k++) {
            const int colg = k * 32 + hl * 2;
            for (int it = 0; it < 16; it++) {
                int r = it * 8 + pwarp * 2 + half;
                int node = row0 + r;
                float2 acc = make_float2(0.f, 0.f);
                if (node < M) {
                    acc = *(const float2*)(H + (size_t)node * DH + colg);
                    int s = __ldg(off + node);
                    int e = s + __ldg(deg + node);
                    int j = s;
                    for (; j + 4 <= e; j += 4) {
                        int i0 = __ldg(csr + j), i1 = __ldg(csr + j + 1);
                        int i2 = __ldg(csr + j + 2), i3 = __ldg(csr + j + 3);
                        float2 v0 = *(const float2*)(H + (size_t)i0 * DH + colg);
                        float2 v1 = *(const float2*)(H + (size_t)i1 * DH + colg);
                        float2 v2 = *(const float2*)(H + (size_t)i2 * DH + colg);
                        float2 v3 = *(const float2*)(H + (size_t)i3 * DH + colg);
                        acc.x += v0.x + v1.x + v2.x + v3.x;
                        acc.y += v0.y + v1.y + v2.y + v3.y;
                    }
                    for (; j < e; j++) {
                        int i0 = __ldg(csr + j);
                        float2 v = *(const float2*)(H + (size_t)i0 * DH + colg);
                        acc.x += v.x; acc.y += v.y;
                    }
                }
                uint32_t hi, lo;
                split2(acc.x, acc.y, hi, lo);
                uint32_t ob = swz64((uint32_t)(r * 64 + hl * 4));
                *(uint32_t*)(smem + k * 16384 + ob) = hi;
                *(uint32_t*)(smem + k * 16384 + 8192 + ob) = lo;
            }
            __threadfence_block();
            asm volatile("bar.arrive %0, 384;" :: "r"(1 + k) : "memory");
        }
        return;
    }

    // ---------------- consumer warps: 8-warp MMA, nb-loop over 4 N-blocks ----------------
    const int lane = tid & 31;
    const int w = tid >> 5;
    const int wn = w & 3;                 // WN_CNT = 4 (WN=32)
    const int wm = w >> 2;                // 0..1    (WM=64)
    const int lrow = lane & 15;
    const int lcolb = ((lane >> 4) & 1) * 16;
    const uint32_t bbase = sbase + 65536;

    auto load_B = [&](int s, int it2) {
        const int nb2 = it2 >> 2, k2 = it2 & 3;
        const uint32_t st = bbase + (uint32_t)s * 16384;
        const int col0 = nb2 * 128;
#pragma unroll
        for (int gid = tid; gid < 512; gid += 256) {
            int r = gid >> 2, g = gid & 3;
            size_t o = (size_t)(col0 + r) * DH + k2 * 32 + g * 8;
            uint32_t d = st + swz64((uint32_t)(r * 64 + g * 16));
            cpasync16(d, Bhi + o, true);
            cpasync16(d + 8192, Blo + o, true);
        }
    };

    float acc[4][4][4];
#pragma unroll
    for (int i = 0; i < 4; i++)
#pragma unroll
        for (int j = 0; j < 4; j++)
#pragma unroll
            for (int q = 0; q < 4; q++) acc[i][j][q] = 0.f;

    load_B(0, 0); cp_commit();
    load_B(1, 1); cp_commit();

    for (int it = 0; it < 16; ++it) {
        const int nb = it >> 2, k = it & 3;
        cp_wait<1>();
        asm volatile("bar.sync 5, 256;" ::: "memory");   // B stage ready + old stage free
        if (it + 2 < 16) load_B((it + 2) % 3, it + 2);
        cp_commit();
        if (nb == 0)
            asm volatile("bar.sync %0, 384;" :: "r"(1 + k) : "memory");  // A chunk k ready

        const uint32_t bAhi = sbase + (uint32_t)k * 16384;
        const uint32_t bAlo = bAhi + 8192;
        const uint32_t bBhi = bbase + (uint32_t)(it % 3) * 16384;
        const uint32_t bBlo = bBhi + 8192;
#pragma unroll
        for (int ks = 0; ks < 2; ks++) {
            uint32_t ahi[4][4], alo[4][4];
            uint32_t bhi[4][2], blo[4][2];
#pragma unroll
            for (int mf = 0; mf < 4; mf++) {
                uint32_t o = swz64((uint32_t)(wm * 64 + mf * 16 + lrow) * 64
                                   + ks * 32 + lcolb);
                ldsm4(bAhi + o, ahi[mf]);
                ldsm4(bAlo + o, alo[mf]);
            }
#pragma unroll
            for (int nf2 = 0; nf2 < 2; nf2++) {
                uint32_t o = swz64((uint32_t)(wn * 32 + nf2 * 16 + lrow) * 64
                                   + ks * 32 + lcolb);
                uint32_t r4[4];
                ldsm4(bBhi + o, r4);
                bhi[nf2 * 2 + 0][0] = r4[0]; bhi[nf2 * 2 + 1][0] = r4[1];
                bhi[nf2 * 2 + 0][1] = r4[2]; bhi[nf2 * 2 + 1][1] = r4[3];
                ldsm4(bBlo + o, r4);
                blo[nf2 * 2 + 0][0] = r4[0]; blo[nf2 * 2 + 1][0] = r4[1];
                blo[nf2 * 2 + 0][1] = r4[2]; blo[nf2 * 2 + 1][1] = r4[3];
            }
#pragma unroll
            for (int mf = 0; mf < 4; mf++)
#pragma unroll
                for (int nf = 0; nf < 4; nf++) {
                    mma_bf16(acc[mf][nf], ahi[mf], bhi[nf]);
                    mma_bf16(acc[mf][nf], ahi[mf], blo[nf]);
                    mma_bf16(acc[mf][nf], alo[mf], bhi[nf]);
                }
        }

        if (k == 3) {
            const int col0 = nb * 128;
#pragma unroll
            for (int mf = 0; mf < 4; mf++) {
#pragma unroll
                for (int nf = 0; nf < 4; nf++) {
                    int r = row0 + wm * 64 + mf * 16 + (lane >> 2);
                    int c = col0 + wn * 32 + nf * 8 + (lane & 3) * 2;
                    float b0 = __ldg(bias + c), b1 = __ldg(bias + c + 1);
#pragma unroll
                    for (int hlf = 0; hlf < 2; hlf++) {
                        int rr = r + hlf * 8;
                        if (rr >= M) continue;
                        float v0 = fmaxf(acc[mf][nf][hlf * 2 + 0] + b0, 0.f);
                        float v1 = fmaxf(acc[mf][nf][hlf * 2 + 1] + b1, 0.f);
                        uint32_t hi, lo;
                        split2(v0, v1, hi, lo);
                        size_t o = (size_t)rr * DMLP + c;
                        *(uint32_t*)(Chi + o) = hi;
                        *(uint32_t*)(Clo + o) = lo;
                    }
#pragma unroll
                    for (int q = 0; q < 4; q++) acc[mf][nf][q] = 0.f;
                }
            }
        }
    }
}

// ---------------- split-bf16 tensor-core GEMM (round-12 proven; GEMM2) ----------------
template<int BM, int BN, int WM, int WN, int STAGES, bool SPLIT_OUT>
__global__ void __launch_bounds__((BM / WM) * (BN / WN) * 32)
bf3_gemm(const __nv_bfloat16* __restrict__ Ahi, const __nv_bfloat16* __restrict__ Alo,
         const __nv_bfloat16* __restrict__ Bhi, const __nv_bfloat16* __restrict__ Blo,
         const float* __restrict__ bias,
         float* __restrict__ C, __nv_bfloat16* __restrict__ Chi, __nv_bfloat16* __restrict__ Clo,
         int M, int N, int K) {
    constexpr int THREADS = (BM / WM) * (BN / WN) * 32;
    constexpr int BK = 32;
    constexpr int ATB = BM * BK * 2;
    constexpr int BTB = BN * BK * 2;
    constexpr int STAGE = 2 * ATB + 2 * BTB;
    constexpr int AG = BM * 4;
    constexpr int BG = BN * 4;
    constexpr int MF = WM / 16;
    constexpr int NF = WN / 8;

    extern __shared__ char smem[];
    const uint32_t sbase = (uint32_t)__cvta_generic_to_shared(smem);

    const int tid = threadIdx.x;
    const int lane = tid & 31;
    const int w = tid >> 5;
    constexpr int WN_CNT = BN / WN;
    const int wn = w % WN_CNT;
    const int wm = w / WN_CNT;
    const int row0 = blockIdx.x * BM;
    const int col0 = blockIdx.y * BN;
    const int T = K / BK;

    float acc[MF][NF][4];
#pragma unroll
    for (int i = 0; i < MF; i++)
#pragma unroll
        for (int j = 0; j < NF; j++)
#pragma unroll
            for (int q = 0; q < 4; q++) acc[i][j][q] = 0.f;

    auto load_stage = [&](int s, int t) {
        const uint32_t st = sbase + s * STAGE;
        const int k0 = t * BK;
#pragma unroll
        for (int gid = tid; gid < AG; gid += THREADS) {
            int r = gid >> 2, g = gid & 3;
            bool p = (row0 + r) < M;
            size_t off = (size_t)(row0 + r) * K + k0 + g * 8;
            uint32_t d = st + swz64((uint32_t)(r * 64 + g * 16));
            cpasync16(d, Ahi + off, p);
            cpasync16(d + ATB, Alo + off, p);
        }
#pragma unroll
        for (int gid = tid; gid < BG; gid += THREADS) {
            int r = gid >> 2, g = gid & 3;
            size_t off = (size_t)(col0 + r) * K + k0 + g * 8;
            uint32_t d = st + 2 * ATB + swz64((uint32_t)(r * 64 + g * 16));
            cpasync16(d, Bhi + off, true);
            cpasync16(d + BTB, Blo + off, true);
        }
    };

#pragma unroll
    for (int s = 0; s < STAGES - 1; s++) {
        if (s < T) load_stage(s, s);
        cp_commit();
    }

    const int lrow = lane & 15;
    const int lcolb = ((lane >> 4) & 1) * 16;

    for (int t = 0; t < T; ++t) {
        cp_wait<STAGES - 2>();
        __syncthreads();
        if (t + STAGES - 1 < T) load_stage((t + STAGES - 1) % STAGES, t + STAGES - 1);
        cp_commit();

        const uint32_t st = sbase + (t % STAGES) * STAGE;
        const uint32_t bAhi = st, bAlo = st + ATB;
        const uint32_t bBhi = st + 2 * ATB, bBlo = bBhi + BTB;
#pragma unroll
        for (int ks = 0; ks < 2; ks++) {
            uint32_t ahi[MF][4], alo[MF][4];
            uint32_t bhi[NF][2], blo[NF][2];
#pragma unroll
            for (int mf = 0; mf < MF; mf++) {
                uint32_t off = swz64((uint32_t)(wm * WM + mf * 16 + lrow) * 64
                                     + ks * 32 + lcolb);
                ldsm4(bAhi + off, ahi[mf]);
                ldsm4(bAlo + off, alo[mf]);
            }
#pragma unroll
            for (int nf2 = 0; nf2 < NF / 2; nf2++) {
                uint32_t off = swz64((uint32_t)(wn * WN + nf2 * 16 + lrow) * 64
                                     + ks * 32 + lcolb);
                uint32_t r4[4];
                ldsm4(bBhi + off, r4);
                bhi[nf2 * 2 + 0][0] = r4[0]; bhi[nf2 * 2 + 1][0] = r4[1];
                bhi[nf2 * 2 + 0][1] = r4[2]; bhi[nf2 * 2 + 1][1] = r4[3];
                ldsm4(bBlo + off, r4);
                blo[nf2 * 2 + 0][0] = r4[0]; blo[nf2 * 2 + 1][0] = r4[1];
                blo[nf2 * 2 + 0][1] = r4[2]; blo[nf2 * 2 + 1][1] = r4[3];
            }
#pragma unroll
            for (int mf = 0; mf < MF; mf++)
#pragma unroll
                for (int nf = 0; nf < NF; nf++) {
                    mma_bf16(acc[mf][nf], ahi[mf], bhi[nf]);
                    mma_bf16(acc[mf][nf], ahi[mf], blo[nf]);
                    mma_bf16(acc[mf][nf], alo[mf], bhi[nf]);
                }
        }
    }

#pragma unroll
    for (int mf = 0; mf < MF; mf++) {
#pragma unroll
        for (int nf = 0; nf < NF; nf++) {
            int r = row0 + wm * WM + mf * 16 + (lane >> 2);
            int c = col0 + wn * WN + nf * 8 + (lane & 3) * 2;
            float b0 = __ldg(bias + c), b1 = __ldg(bias + c + 1);
#pragma unroll
            for (int half = 0; half < 2; half++) {
                int rr = r + half * 8;
                if (rr >= M) continue;
                float v0 = fmaxf(acc[mf][nf][half * 2 + 0] + b0, 0.f);
                float v1 = fmaxf(acc[mf][nf][half * 2 + 1] + b1, 0.f);
                size_t o = (size_t)rr * N + c;
                if (SPLIT_OUT) {
                    uint32_t hi, lo;
                    split2(v0, v1, hi, lo);
                    *(uint32_t*)(Chi + o) = hi;
                    *(uint32_t*)(Clo + o) = lo;
                } else {
                    *(float2*)(C + o) = make_float2(v0, v1);
                }
            }
        }
    }
}

// ================ predictor GEMM with fused matvec epilogue ================
__global__ void __launch_bounds__(128)
pred_gemm(const __nv_bfloat16* __restrict__ Ahi, const __nv_bfloat16* __restrict__ Alo,
          const __nv_bfloat16* __restrict__ Bhi, const __nv_bfloat16* __restrict__ Blo,
          const float* __restrict__ bp1, const float* __restrict__ Wp2,
          const float* __restrict__ bp2, float* __restrict__ out,
          int M, int K) {
    constexpr int BM = 128, BN = 64, WM = 64, WN = 32, STAGES = 3, BK = 32;
    constexpr int THREADS = 128;
    constexpr int ATB = BM * BK * 2;
    constexpr int BTB = BN * BK * 2;
    constexpr int STAGE = 2 * ATB + 2 * BTB;
    constexpr int AG = BM * 4;
    constexpr int BG = BN * 4;
    constexpr int MF = WM / 16;
    constexpr int NF = WN / 8;

    extern __shared__ char smem[];
    const uint32_t sbase = (uint32_t)__cvta_generic_to_shared(smem);
    float* sred = (float*)smem;

    const int tid = threadIdx.x;
    const int lane = tid & 31;
    const int w = tid >> 5;
    const int wn = w & 1;
    const int wm = w >> 1;
    const int row0 = blockIdx.x * BM;
    const int T = K / BK;

    const int lrow = lane & 15;
    const int lcolb = ((lane >> 4) & 1) * 16;

    float acc[MF][NF][4];
#pragma unroll
    for (int i = 0; i < MF; i++)
#pragma unroll
        for (int j = 0; j < NF; j++)
#pragma unroll
            for (int q = 0; q < 4; q++) acc[i][j][q] = 0.f;

    auto load_stage = [&](int s, int t) {
        const uint32_t st = sbase + s * STAGE;
        const int k0 = t * BK;
#pragma unroll
        for (int gid = tid; gid < AG; gid += THREADS) {
            int r = gid >> 2, g = gid & 3;
            bool p = (row0 + r) < M;
            size_t off = (size_t)(row0 + r) * K + k0 + g * 8;
            uint32_t d = st + swz64((uint32_t)(r * 64 + g * 16));
            cpasync16(d, Ahi + off, p);
            cpasync16(d + ATB, Alo + off, p);
        }
#pragma unroll
        for (int gid = tid; gid < BG; gid += THREADS) {
            int r = gid >> 2, g = gid & 3;
            size_t off = (size_t)r * K + k0 + g * 8;
            uint32_t d = st + 2 * ATB + swz64((uint32_t)(r * 64 + g * 16));
            cpasync16(d, Bhi + off, true);
            cpasync16(d + BTB, Blo + off, true);
        }
    };

#pragma unroll
    for (int s = 0; s < STAGES - 1; s++) {
        if (s < T) load_stage(s, s);
        cp_commit();
    }

    for (int t = 0; t < T; ++t) {
        cp_wait<STAGES - 2>();
        __syncthreads();
        if (t + STAGES - 1 < T) load_stage((t + STAGES - 1) % STAGES, t + STAGES - 1);
        cp_commit();

        const uint32_t st = sbase + (t % STAGES) * STAGE;
        const uint32_t bAhi = st, bAlo = st + ATB;
        const uint32_t bBhi = st + 2 * ATB, bBlo = bBhi + BTB;
#pragma unroll
        for (int ks = 0; ks < 2; ks++) {
            uint32_t ahi[MF][4], alo[MF][4];
            uint32_t bhi[NF][2], blo[NF][2];
#pragma unroll
            for (int mf = 0; mf < MF; mf++) {
                uint32_t off = swz64((uint32_t)(wm * WM + mf * 16 + lrow) * 64
                                     + ks * 32 + lcolb);
                ldsm4(bAhi + off, ahi[mf]);
                ldsm4(bAlo + off, alo[mf]);
            }
#pragma unroll
            for (int nf2 = 0; nf2 < NF / 2; nf2++) {
                uint32_t off = swz64((uint32_t)(wn * WN + nf2 * 16 + lrow) * 64
                                     + ks * 32 + lcolb);
                uint32_t r4[4];
                ldsm4(bBhi + off, r4);
                bhi[nf2 * 2 + 0][0] = r4[0]; bhi[nf2 * 2 + 1][0] = r4[1];
                bhi[nf2 * 2 + 0][1] = r4[2]; bhi[nf2 * 2 + 1][1] = r4[3];
                ldsm4(bBlo + off, r4);
                blo[nf2 * 2 + 0][0] = r4[0]; blo[nf2 * 2 + 1][0] = r4[1];
                blo[nf2 * 2 + 0][1] = r4[2]; blo[nf2 * 2 + 1][1] = r4[3];
            }
#pragma unroll
            for (int mf = 0; mf < MF; mf++)
#pragma unroll
                for (int nf = 0; nf < NF; nf++) {
                    mma_bf16(acc[mf][nf], ahi[mf], bhi[nf]);
                    mma_bf16(acc[mf][nf], ahi[mf], blo[nf]);
                    mma_bf16(acc[mf][nf], alo[mf], bhi[nf]);
                }
        }
    }
    __syncthreads();   // all warps done with mainloop smem before sred reuse

#pragma unroll
    for (int mf = 0; mf < MF; mf++) {
        float part0 = 0.f, part1 = 0.f;
#pragma unroll
        for (int nf = 0; nf < NF; nf++) {
            int c = wn * WN + nf * 8 + (lane & 3) * 2;
            float b0 = __ldg(bp1 + c), b1 = __ldg(bp1 + c + 1);
            float w0 = __ldg(Wp2 + c), w1 = __ldg(Wp2 + c + 1);
            part0 += fmaxf(acc[mf][nf][0] + b0, 0.f) * w0
                   + fmaxf(acc[mf][nf][1] + b1, 0.f) * w1;
            part1 += fmaxf(acc[mf][nf][2] + b0, 0.f) * w0
                   + fmaxf(acc[mf][nf][3] + b1, 0.f) * w1;
        }
#pragma unroll
        for (int o = 1; o < 4; o <<= 1) {
            part0 += __shfl_xor_sync(0xffffffffu, part0, o);
            part1 += __shfl_xor_sync(0xffffffffu, part1, o);
        }
        if ((lane & 3) == 0) {
            int lr = wm * WM + mf * 16 + (lane >> 2);
            sred[wn * 128 + lr] = part0;
            sred[wn * 128 + lr + 8] = part1;
        }
    }
    __syncthreads();
    {
        int r = row0 + tid;
        if (r < M) out[r] = sred[tid] + sred[128 + tid] + __ldg(bp2);
    }
}

// ---------------- predictor: build V rows = h[src]*h[dst], split to bf16 ----------------
__global__ void build_v_kernel(const float* __restrict__ h,
                               const int* __restrict__ psrc, const int* __restrict__ pdst,
                               const int* __restrict__ nsrc, const int* __restrict__ ndst,
                               __nv_bfloat16* __restrict__ Vh,
                               __nv_bfloat16* __restrict__ Vl, int P) {
    int idx = blockIdx.x * blockDim.x + threadIdx.x;
    int p = idx >> 5;
    if (p >= 2 * P) return;
    int c = (idx & 31) << 2;
    int s, d;
    if (p < P) { s = __ldg(psrc + p); d = __ldg(pdst + p); }
    else       { s = __ldg(nsrc + p - P); d = __ldg(ndst + p - P); }
    float4 a = *(const float4*)(h + (size_t)s * DH + c);
    float4 b = *(const float4*)(h + (size_t)d * DH + c);
    uint32_t h0, h1, l0, l1;
    split2(a.x * b.x, a.y * b.y, h0, l0);
    split2(a.z * b.z, a.w * b.w, h1, l1);
    size_t o = (size_t)p * DH + c;
    *(uint2*)(Vh + o) = make_uint2(h0, h1);
    *(uint2*)(Vl + o) = make_uint2(l0, l1);
}

// ---------------- launch ----------------
extern "C" void kernel_launch(void* const* d_in, const int* in_sizes, int n_in,
                              void* d_out, int out_size) {
    const float* x    = (const float*)d_in[0];
    const float* W1   = (const float*)d_in[1];
    const float* b1   = (const float*)d_in[2];
    const float* W2   = (const float*)d_in[3];
    const float* b2   = (const float*)d_in[4];
    const float* Wp1  = (const float*)d_in[5];
    const float* bp1  = (const float*)d_in[6];
    const float* Wp2  = (const float*)d_in[7];
    const float* bp2  = (const float*)d_in[8];
    const int*   esrc = (const int*)d_in[9];
    const int*   edst = (const int*)d_in[10];
    const int*   psrc = (const int*)d_in[11];
    const int*   pdst = (const int*)d_in[12];
    const int*   nsrc = (const int*)d_in[13];
    const int*   ndst = (const int*)d_in[14];
    float* out = (float*)d_out;

    float *hbuf, *z;
    __nv_bfloat16 *w1h, *w1l, *w2h, *w2l, *wp1h, *wp1l;
    int *deg, *incl, *off, *cur, *bsum, *csr;
    cudaGetSymbolAddress((void**)&hbuf, g_h);
    cudaGetSymbolAddress((void**)&z,    g_z);
    cudaGetSymbolAddress((void**)&w1h,  g_w1h);
    cudaGetSymbolAddress((void**)&w1l,  g_w1l);
    cudaGetSymbolAddress((void**)&w2h,  g_w2h);
    cudaGetSymbolAddress((void**)&w2l,  g_w2l);
    cudaGetSymbolAddress((void**)&wp1h, g_wp1h);
    cudaGetSymbolAddress((void**)&wp1l, g_wp1l);
    cudaGetSymbolAddress((void**)&deg,  g_deg);
    cudaGetSymbolAddress((void**)&incl, g_incl);
    cudaGetSymbolAddress((void**)&off,  g_off);
    cudaGetSymbolAddress((void**)&cur,  g_cur);
    cudaGetSymbolAddress((void**)&bsum, g_bsum);
    cudaGetSymbolAddress((void**)&csr,  g_csr);

    __nv_bfloat16* zh = (__nv_bfloat16*)z;
    __nv_bfloat16* zl = zh + (size_t)NN * DMLP;
    __nv_bfloat16* vh = (__nv_bfloat16*)z;
    __nv_bfloat16* vl = vh + (size_t)2 * PP * DH;

    constexpr int SMEM_MAIN = 3 * 2 * (128 + 128) * 32 * 2;   // 96 KB
    constexpr int SMEM_PRED = 3 * 2 * (128 + 64) * 32 * 2;    // 72 KB
    cudaFuncSetAttribute(fused_gemm1,
                         cudaFuncAttributeMaxDynamicSharedMemorySize, FG1_SMEM);
    cudaFuncSetAttribute(bf3_gemm<128, 128, 64, 32, 3, false>,
                         cudaFuncAttributeMaxDynamicSharedMemorySize, SMEM_MAIN);
    cudaFuncSetAttribute(pred_gemm,
                         cudaFuncAttributeMaxDynamicSharedMemorySize, SMEM_PRED);

    float* out_h = out + 2 * PP;   // final h ([N,128]) lives in output

    // ---- fork: weight transposes on a side stream, CSR build on the main stream ----
    cudaStream_t s2;
    cudaStreamCreateWithFlags(&s2, cudaStreamNonBlocking);
    cudaEvent_t evFork, evJoin;
    cudaEventCreateWithFlags(&evFork, cudaEventDisableTiming);
    cudaEventCreateWithFlags(&evJoin, cudaEventDisableTiming);

    cudaEventRecord(evFork, 0);
    cudaStreamWaitEvent(s2, evFork, 0);
    transpose_split_kernel<<<dim3(DMLP / 32, DH / 32, LAYERS), dim3(32, 32), 0, s2>>>(
        W1, w1h, w1l, DH, DMLP);
    transpose_split_kernel<<<dim3(DH / 32, DMLP / 32, LAYERS), dim3(32, 32), 0, s2>>>(
        W2, w2h, w2l, DMLP, DH);
    transpose_split_kernel<<<dim3(DPRED / 32, DH / 32, 1), dim3(32, 32), 0, s2>>>(
        Wp1, wp1h, wp1l, DH, DPRED);
    cudaEventRecord(evJoin, s2);

    // ---- CSR build (main stream, parallel with transposes) ----
    zero_int_kernel<<<cdiv(NN, 256), 256>>>(deg, NN);
    hist_kernel<<<cdiv(EE, 256), 256>>>(edst, deg, EE);
    scan_block_kernel<<<SCAN_NB, SCAN_B>>>(deg, incl, bsum, NN);
    scan_sums_kernel<<<1, 128>>>(bsum, SCAN_NB);
    finalize_off_kernel<<<cdiv(NN, 256), 256>>>(incl, deg, bsum, off, cur, NN);
    fill_kernel<<<cdiv(EE, 256), 256>>>(esrc, edst, cur, csr, EE);

    cudaStreamWaitEvent(0, evJoin, 0);   // join before GEMMs consume weights

    const int M = NN;
    for (int l = 0; l < LAYERS; l++) {
        const float* hcur = (l == 0) ? x : hbuf;
        float* hnext = (l == LAYERS - 1) ? out_h : hbuf;

        // fused: gather(h) + z = relu(agg @ W1 + b1), split bf16 out
        fused_gemm1<<<cdiv(M, 128), 384, FG1_SMEM>>>(
            hcur, off, deg, csr,
            w1h + (size_t)l * DMLP * DH, w1l + (size_t)l * DMLP * DH,
            b1 + (size_t)l * DMLP, zh, zl, M);
        // h = relu(z @ W2 + b2), fp32 out
        bf3_gemm<128, 128, 64, 32, 3, false>
            <<<dim3(cdiv(M, 128), 1), 256, SMEM_MAIN>>>(
                zh, zl, w2h + (size_t)l * DH * DMLP, w2l + (size_t)l * DH * DMLP,
                b2 + (size_t)l * DH, hnext, nullptr, nullptr, M, DH, DMLP);
    }

    // ---- predictor: V build, then fused GEMM + matvec epilogue ----
    build_v_kernel<<<cdiv(2 * PP * 32, 256), 256>>>(out_h, psrc, pdst, nsrc, ndst, vh, vl, PP);
    pred_gemm<<<cdiv(2 * PP, 128), 128, SMEM_PRED>>>(
        vh, vl, wp1h, wp1l, bp1, Wp2, bp2, out, 2 * PP, DH);
}

// round 17
// speedup vs baseline: 3.3604x; 3.3604x over previous
#include <cuda_runtime.h>
#include <cuda_bf16.h>
#include <cstdint>

#define NN 100000      // nodes
#define EE 1600000     // edges
#define PP 100000      // pairs (each of pos/neg)
#define DH 128
#define DMLP 512
#define DPRED 64
#define LAYERS 3
#define SCAN_B 1024
#define SCAN_NB ((NN + SCAN_B - 1) / SCAN_B)   // 98

// ---------------- scratch (static device allocations) ----------------
__device__ float g_h[(size_t)NN * DH];                   // fp32 h between layers
__device__ float g_z[(size_t)NN * DMLP];                 // aliased: zh/zl bf16, or Vhi/Vlo
__device__ __nv_bfloat16 g_ah[(size_t)NN * DH];          // agg hi
__device__ __nv_bfloat16 g_al[(size_t)NN * DH];          // agg lo
__device__ __nv_bfloat16 g_w1h[LAYERS * DMLP * DH], g_w1l[LAYERS * DMLP * DH];
__device__ __nv_bfloat16 g_w2h[LAYERS * DH * DMLP], g_w2l[LAYERS * DH * DMLP];
__device__ __nv_bfloat16 g_wp1h[DPRED * DH], g_wp1l[DPRED * DH];
// CSR scratch
__device__ int g_deg[NN];
__device__ int g_incl[NN];
__device__ int g_off[NN];
__device__ int g_cur[NN];
__device__ int g_bsum[128];
__device__ int g_csr[EE];

static inline int cdiv(int a, int b) { return (a + b - 1) / b; }

// ---------------- common helpers ----------------
__device__ __forceinline__ uint32_t swz64(uint32_t off) { return off ^ ((off >> 3) & 0x30u); }

__device__ __forceinline__ void cpasync16(uint32_t dst, const void* src, bool pred) {
    asm volatile("cp.async.cg.shared.global [%0], [%1], 16, %2;"
                 :: "r"(dst), "l"(src), "r"(pred ? 16 : 0) : "memory");
}
__device__ __forceinline__ void cp_commit() {
    asm volatile("cp.async.commit_group;" ::: "memory");
}
template<int N> __device__ __forceinline__ void cp_wait() {
    asm volatile("cp.async.wait_group %0;" :: "n"(N) : "memory");
}

__device__ __forceinline__ void split2(float a, float b, uint32_t& hi, uint32_t& lo) {
    __nv_bfloat16 ha = __float2bfloat16(a), hb = __float2bfloat16(b);
    __nv_bfloat16 la = __float2bfloat16(a - __bfloat162float(ha));
    __nv_bfloat16 lb = __float2bfloat16(b - __bfloat162float(hb));
    __nv_bfloat162 h = __halves2bfloat162(ha, hb), l = __halves2bfloat162(la, lb);
    hi = *reinterpret_cast<uint32_t*>(&h);
    lo = *reinterpret_cast<uint32_t*>(&l);
}

__device__ __forceinline__ void mma_bf16(float* c, const uint32_t* a, const uint32_t* b) {
    asm volatile("mma.sync.aligned.m16n8k16.row.col.f32.bf16.bf16.f32 "
                 "{%0,%1,%2,%3}, {%4,%5,%6,%7}, {%8,%9}, {%0,%1,%2,%3};"
                 : "+f"(c[0]), "+f"(c[1]), "+f"(c[2]), "+f"(c[3])
                 : "r"(a[0]), "r"(a[1]), "r"(a[2]), "r"(a[3]), "r"(b[0]), "r"(b[1]));
}
__device__ __forceinline__ void ldsm4(uint32_t addr, uint32_t* r) {
    asm volatile("ldmatrix.sync.aligned.m8n8.x4.shared.b16 {%0,%1,%2,%3}, [%4];"
                 : "=r"(r[0]), "=r"(r[1]), "=r"(r[2]), "=r"(r[3]) : "r"(addr));
}

// ---------------- CSR build kernels ----------------
__global__ void zero_int_kernel(int* __restrict__ p, int n) {
    int i = blockIdx.x * blockDim.x + threadIdx.x;
    if (i < n) p[i] = 0;
}
__global__ void hist_kernel(const int* __restrict__ dst, int* __restrict__ deg, int E) {
    int e = blockIdx.x * blockDim.x + threadIdx.x;
    if (e < E) atomicAdd(&deg[__ldg(dst + e)], 1);
}
__global__ void scan_block_kernel(const int* __restrict__ deg, int* __restrict__ incl,
                                  int* __restrict__ bsum, int n) {
    __shared__ int sm[SCAN_B];
    int i = blockIdx.x * SCAN_B + threadIdx.x;
    int v = (i < n) ? deg[i] : 0;
    sm[threadIdx.x] = v;
    __syncthreads();
    for (int o = 1; o < SCAN_B; o <<= 1) {
        int t = (threadIdx.x >= o) ? sm[threadIdx.x - o] : 0;
        __syncthreads();
        sm[threadIdx.x] += t;
        __syncthreads();
    }
    if (i < n) incl[i] = sm[threadIdx.x];
    if (threadIdx.x == SCAN_B - 1) bsum[blockIdx.x] = sm[SCAN_B - 1];
}
__global__ void scan_sums_kernel(int* __restrict__ bsum, int nb) {
    __shared__ int sm[128];
    int v = (threadIdx.x < nb) ? bsum[threadIdx.x] : 0;
    sm[threadIdx.x] = v;
    __syncthreads();
    for (int o = 1; o < 128; o <<= 1) {
        int t = (threadIdx.x >= o) ? sm[threadIdx.x - o] : 0;
        __syncthreads();
        sm[threadIdx.x] += t;
        __syncthreads();
    }
    if (threadIdx.x < nb) bsum[threadIdx.x] = sm[threadIdx.x] - v;   // exclusive
}
__global__ void finalize_off_kernel(const int* __restrict__ incl, const int* __restrict__ deg,
                                    const int* __restrict__ bsum,
                                    int* __restrict__ off, int* __restrict__ cur, int n) {
    int i = blockIdx.x * blockDim.x + threadIdx.x;
    if (i >= n) return;
    int o = incl[i] - deg[i] + bsum[i / SCAN_B];
    off[i] = o;
    cur[i] = o;
}
__global__ void fill_kernel(const int* __restrict__ src, const int* __restrict__ dst,
                            int* __restrict__ cur, int* __restrict__ csr, int E) {
    int e = blockIdx.x * blockDim.x + threadIdx.x;
    if (e >= E) return;
    int p = atomicAdd(&cur[__ldg(dst + e)], 1);
    csr[p] = __ldg(src + e);
}

// ---------------- gather + self + bf16 split (warp per node) ----------------
__global__ void gather_split_kernel(const float* __restrict__ h,
                                    const int* __restrict__ off, const int* __restrict__ deg,
                                    const int* __restrict__ csr,
                                    __nv_bfloat16* __restrict__ ah,
                                    __nv_bfloat16* __restrict__ al, int n) {
    int widx = (blockIdx.x * blockDim.x + threadIdx.x) >> 5;
    if (widx >= n) return;
    int c = (threadIdx.x & 31) << 2;
    float4 acc = *(const float4*)(h + (size_t)widx * DH + c);
    int s = __ldg(off + widx);
    int e = s + __ldg(deg + widx);
    int j = s;
    for (; j + 4 <= e; j += 4) {
        int i0 = __ldg(csr + j), i1 = __ldg(csr + j + 1);
        int i2 = __ldg(csr + j + 2), i3 = __ldg(csr + j + 3);
        float4 v0 = *(const float4*)(h + (size_t)i0 * DH + c);
        float4 v1 = *(const float4*)(h + (size_t)i1 * DH + c);
        float4 v2 = *(const float4*)(h + (size_t)i2 * DH + c);
        float4 v3 = *(const float4*)(h + (size_t)i3 * DH + c);
        acc.x += v0.x + v1.x + v2.x + v3.x;
        acc.y += v0.y + v1.y + v2.y + v3.y;
        acc.z += v0.z + v1.z + v2.z + v3.z;
        acc.w += v0.w + v1.w + v2.w + v3.w;
    }
    for (; j < e; j++) {
        int i0 = __ldg(csr + j);
        float4 v0 = *(const float4*)(h + (size_t)i0 * DH + c);
        acc.x += v0.x; acc.y += v0.y; acc.z += v0.z; acc.w += v0.w;
    }
    uint32_t h0, h1, l0, l1;
    split2(acc.x, acc.y, h0, l0);
    split2(acc.z, acc.w, h1, l1);
    size_t o = (size_t)widx * DH + c;
    *(uint2*)(ah + o) = make_uint2(h0, h1);
    *(uint2*)(al + o) = make_uint2(l0, l1);
}

// in[b][R][C] fp32 -> outh/outl [b][C][R] bf16 (transpose + split); R,C multiples of 32
__global__ void transpose_split_kernel(const float* __restrict__ in,
                                       __nv_bfloat16* __restrict__ outh,
                                       __nv_bfloat16* __restrict__ outl, int R, int C) {
    __shared__ float tile[32][33];
    const float* ib = in + (size_t)blockIdx.z * R * C;
    int r = blockIdx.y * 32 + threadIdx.y;
    int c = blockIdx.x * 32 + threadIdx.x;
    tile[threadIdx.y][threadIdx.x] = ib[(size_t)r * C + c];
    __syncthreads();
    int ro = blockIdx.x * 32 + threadIdx.y;
    int co = blockIdx.y * 32 + threadIdx.x;
    float v = tile[threadIdx.x][threadIdx.y];
    __nv_bfloat16 h = __float2bfloat16(v);
    __nv_bfloat16 l = __float2bfloat16(v - __bfloat162float(h));
    size_t o = (size_t)blockIdx.z * R * C + (size_t)ro * R + co;
    outh[o] = h;
    outl[o] = l;
}

// ---------------- split-bf16 tensor-core GEMM, cp.async multistage ----------------
// Single __syncthreads per mainloop iteration: the top sync (after cp_wait) both
// publishes the arrived stage and guarantees all warps finished computing the
// stage about to be overwritten (it was computed at iteration t-1, before this barrier).
template<int BM, int BN, int WM, int WN, int STAGES, bool SPLIT_OUT>
__global__ void __launch_bounds__((BM / WM) * (BN / WN) * 32)
bf3_gemm(const __nv_bfloat16* __restrict__ Ahi, const __nv_bfloat16* __restrict__ Alo,
         const __nv_bfloat16* __restrict__ Bhi, const __nv_bfloat16* __restrict__ Blo,
         const float* __restrict__ bias,
         float* __restrict__ C, __nv_bfloat16* __restrict__ Chi, __nv_bfloat16* __restrict__ Clo,
         int M, int N, int K) {
    constexpr int THREADS = (BM / WM) * (BN / WN) * 32;
    constexpr int BK = 32;
    constexpr int ATB = BM * BK * 2;
    constexpr int BTB = BN * BK * 2;
    constexpr int STAGE = 2 * ATB + 2 * BTB;
    constexpr int AG = BM * 4;
    constexpr int BG = BN * 4;
    constexpr int MF = WM / 16;
    constexpr int NF = WN / 8;

    extern __shared__ char smem[];
    const uint32_t sbase = (uint32_t)__cvta_generic_to_shared(smem);

    const int tid = threadIdx.x;
    const int lane = tid & 31;
    const int w = tid >> 5;
    constexpr int WN_CNT = BN / WN;
    const int wn = w % WN_CNT;
    const int wm = w / WN_CNT;
    const int row0 = blockIdx.x * BM;
    const int col0 = blockIdx.y * BN;
    const int T = K / BK;

    float acc[MF][NF][4];
#pragma unroll
    for (int i = 0; i < MF; i++)
#pragma unroll
        for (int j = 0; j < NF; j++)
#pragma unroll
            for (int q = 0; q < 4; q++) acc[i][j][q] = 0.f;

    auto load_stage = [&](int s, int t) {
        const uint32_t st = sbase + s * STAGE;
        const int k0 = t * BK;
#pragma unroll
        for (int gid = tid; gid < AG; gid += THREADS) {
            int r = gid >> 2, g = gid & 3;
            bool p = (row0 + r) < M;
            size_t off = (size_t)(row0 + r) * K + k0 + g * 8;
            uint32_t d = st + swz64((uint32_t)(r * 64 + g * 16));
            cpasync16(d, Ahi + off, p);
            cpasync16(d + ATB, Alo + off, p);
        }
#pragma unroll
        for (int gid = tid; gid < BG; gid += THREADS) {
            int r = gid >> 2, g = gid & 3;
            size_t off = (size_t)(col0 + r) * K + k0 + g * 8;
            uint32_t d = st + 2 * ATB + swz64((uint32_t)(r * 64 + g * 16));
            cpasync16(d, Bhi + off, true);
            cpasync16(d + BTB, Blo + off, true);
        }
    };

#pragma unroll
    for (int s = 0; s < STAGES - 1; s++) {
        if (s < T) load_stage(s, s);
        cp_commit();
    }

    const int lrow = lane & 15;
    const int lcolb = ((lane >> 4) & 1) * 16;

    for (int t = 0; t < T; ++t) {
        cp_wait<STAGES - 2>();
        __syncthreads();   // publishes stage t AND all warps done with the stage we reload below
        if (t + STAGES - 1 < T) load_stage((t + STAGES - 1) % STAGES, t + STAGES - 1);
        cp_commit();

        const uint32_t st = sbase + (t % STAGES) * STAGE;
        const uint32_t bAhi = st, bAlo = st + ATB;
        const uint32_t bBhi = st + 2 * ATB, bBlo = bBhi + BTB;
#pragma unroll
        for (int ks = 0; ks < 2; ks++) {
            uint32_t ahi[MF][4], alo[MF][4];
            uint32_t bhi[NF][2], blo[NF][2];
#pragma unroll
            for (int mf = 0; mf < MF; mf++) {
                uint32_t off = swz64((uint32_t)(wm * WM + mf * 16 + lrow) * 64
                                     + ks * 32 + lcolb);
                ldsm4(bAhi + off, ahi[mf]);
                ldsm4(bAlo + off, alo[mf]);
            }
#pragma unroll
            for (int nf2 = 0; nf2 < NF / 2; nf2++) {
                uint32_t off = swz64((uint32_t)(wn * WN + nf2 * 16 + lrow) * 64
                                     + ks * 32 + lcolb);
                uint32_t r4[4];
                ldsm4(bBhi + off, r4);
                bhi[nf2 * 2 + 0][0] = r4[0]; bhi[nf2 * 2 + 1][0] = r4[1];
                bhi[nf2 * 2 + 0][1] = r4[2]; bhi[nf2 * 2 + 1][1] = r4[3];
                ldsm4(bBlo + off, r4);
                blo[nf2 * 2 + 0][0] = r4[0]; blo[nf2 * 2 + 1][0] = r4[1];
                blo[nf2 * 2 + 0][1] = r4[2]; blo[nf2 * 2 + 1][1] = r4[3];
            }
#pragma unroll
            for (int mf = 0; mf < MF; mf++)
#pragma unroll
                for (int nf = 0; nf < NF; nf++) {
                    mma_bf16(acc[mf][nf], ahi[mf], bhi[nf]);
                    mma_bf16(acc[mf][nf], ahi[mf], blo[nf]);
                    mma_bf16(acc[mf][nf], alo[mf], bhi[nf]);
                }
        }
    }

#pragma unroll
    for (int mf = 0; mf < MF; mf++) {
#pragma unroll
        for (int nf = 0; nf < NF; nf++) {
            int r = row0 + wm * WM + mf * 16 + (lane >> 2);
            int c = col0 + wn * WN + nf * 8 + (lane & 3) * 2;
            float b0 = __ldg(bias + c), b1 = __ldg(bias + c + 1);
#pragma unroll
            for (int half = 0; half < 2; half++) {
                int rr = r + half * 8;
                if (rr >= M) continue;
                float v0 = fmaxf(acc[mf][nf][half * 2 + 0] + b0, 0.f);
                float v1 = fmaxf(acc[mf][nf][half * 2 + 1] + b1, 0.f);
                size_t o = (size_t)rr * N + c;
                if (SPLIT_OUT) {
                    uint32_t hi, lo;
                    split2(v0, v1, hi, lo);
                    *(uint32_t*)(Chi + o) = hi;
                    *(uint32_t*)(Clo + o) = lo;
                } else {
                    *(float2*)(C + o) = make_float2(v0, v1);
                }
            }
        }
    }
}

// ================ predictor GEMM with fused matvec epilogue ================
__global__ void __launch_bounds__(128)
pred_gemm(const __nv_bfloat16* __restrict__ Ahi, const __nv_bfloat16* __restrict__ Alo,
          const __nv_bfloat16* __restrict__ Bhi, const __nv_bfloat16* __restrict__ Blo,
          const float* __restrict__ bp1, const float* __restrict__ Wp2,
          const float* __restrict__ bp2, float* __restrict__ out,
          int M, int K) {
    constexpr int BM = 128, BN = 64, WM = 64, WN = 32, STAGES = 3, BK = 32;
    constexpr int THREADS = 128;
    constexpr int ATB = BM * BK * 2;
    constexpr int BTB = BN * BK * 2;
    constexpr int STAGE = 2 * ATB + 2 * BTB;
    constexpr int AG = BM * 4;
    constexpr int BG = BN * 4;
    constexpr int MF = WM / 16;
    constexpr int NF = WN / 8;

    extern __shared__ char smem[];
    const uint32_t sbase = (uint32_t)__cvta_generic_to_shared(smem);
    float* sred = (float*)smem;

    const int tid = threadIdx.x;
    const int lane = tid & 31;
    const int w = tid >> 5;
    const int wn = w & 1;
    const int wm = w >> 1;
    const int row0 = blockIdx.x * BM;
    const int T = K / BK;

    const int lrow = lane & 15;
    const int lcolb = ((lane >> 4) & 1) * 16;

    float acc[MF][NF][4];
#pragma unroll
    for (int i = 0; i < MF; i++)
#pragma unroll
        for (int j = 0; j < NF; j++)
#pragma unroll
            for (int q = 0; q < 4; q++) acc[i][j][q] = 0.f;

    auto load_stage = [&](int s, int t) {
        const uint32_t st = sbase + s * STAGE;
        const int k0 = t * BK;
#pragma unroll
        for (int gid = tid; gid < AG; gid += THREADS) {
            int r = gid >> 2, g = gid & 3;
            bool p = (row0 + r) < M;
            size_t off = (size_t)(row0 + r) * K + k0 + g * 8;
            uint32_t d = st + swz64((uint32_t)(r * 64 + g * 16));
            cpasync16(d, Ahi + off, p);
            cpasync16(d + ATB, Alo + off, p);
        }
#pragma unroll
        for (int gid = tid; gid < BG; gid += THREADS) {
            int r = gid >> 2, g = gid & 3;
            size_t off = (size_t)r * K + k0 + g * 8;
            uint32_t d = st + 2 * ATB + swz64((uint32_t)(r * 64 + g * 16));
            cpasync16(d, Bhi + off, true);
            cpasync16(d + BTB, Blo + off, true);
        }
    };

#pragma unroll
    for (int s = 0; s < STAGES - 1; s++) {
        if (s < T) load_stage(s, s);
        cp_commit();
    }

    for (int t = 0; t < T; ++t) {
        cp_wait<STAGES - 2>();
        __syncthreads();
        if (t + STAGES - 1 < T) load_stage((t + STAGES - 1) % STAGES, t + STAGES - 1);
        cp_commit();

        const uint32_t st = sbase + (t % STAGES) * STAGE;
        const uint32_t bAhi = st, bAlo = st + ATB;
        const uint32_t bBhi = st + 2 * ATB, bBlo = bBhi + BTB;
#pragma unroll
        for (int ks = 0; ks < 2; ks++) {
            uint32_t ahi[MF][4], alo[MF][4];
            uint32_t bhi[NF][2], blo[NF][2];
#pragma unroll
            for (int mf = 0; mf < MF; mf++) {
                uint32_t off = swz64((uint32_t)(wm * WM + mf * 16 + lrow) * 64
                                     + ks * 32 + lcolb);
                ldsm4(bAhi + off, ahi[mf]);
                ldsm4(bAlo + off, alo[mf]);
            }
#pragma unroll
            for (int nf2 = 0; nf2 < NF / 2; nf2++) {
                uint32_t off = swz64((uint32_t)(wn * WN + nf2 * 16 + lrow) * 64
                                     + ks * 32 + lcolb);
                uint32_t r4[4];
                ldsm4(bBhi + off, r4);
                bhi[nf2 * 2 + 0][0] = r4[0]; bhi[nf2 * 2 + 1][0] = r4[1];
                bhi[nf2 * 2 + 0][1] = r4[2]; bhi[nf2 * 2 + 1][1] = r4[3];
                ldsm4(bBlo + off, r4);
                blo[nf2 * 2 + 0][0] = r4[0]; blo[nf2 * 2 + 1][0] = r4[1];
                blo[nf2 * 2 + 0][1] = r4[2]; blo[nf2 * 2 + 1][1] = r4[3];
            }
#pragma unroll
            for (int mf = 0; mf < MF; mf++)
#pragma unroll
                for (int nf = 0; nf < NF; nf++) {
                    mma_bf16(acc[mf][nf], ahi[mf], bhi[nf]);
                    mma_bf16(acc[mf][nf], ahi[mf], blo[nf]);
                    mma_bf16(acc[mf][nf], alo[mf], bhi[nf]);
                }
        }
    }
    __syncthreads();   // all warps done with mainloop smem before sred reuse

    // ---- fused epilogue: zp = relu(acc + bp1); out = zp . Wp2 + bp2 ----
#pragma unroll
    for (int mf = 0; mf < MF; mf++) {
        float part0 = 0.f, part1 = 0.f;
#pragma unroll
        for (int nf = 0; nf < NF; nf++) {
            int c = wn * WN + nf * 8 + (lane & 3) * 2;
            float b0 = __ldg(bp1 + c), b1 = __ldg(bp1 + c + 1);
            float w0 = __ldg(Wp2 + c), w1 = __ldg(Wp2 + c + 1);
            part0 += fmaxf(acc[mf][nf][0] + b0, 0.f) * w0
                   + fmaxf(acc[mf][nf][1] + b1, 0.f) * w1;
            part1 += fmaxf(acc[mf][nf][2] + b0, 0.f) * w0
                   + fmaxf(acc[mf][nf][3] + b1, 0.f) * w1;
        }
#pragma unroll
        for (int o = 1; o < 4; o <<= 1) {
            part0 += __shfl_xor_sync(0xffffffffu, part0, o);
            part1 += __shfl_xor_sync(0xffffffffu, part1, o);
        }
        if ((lane & 3) == 0) {
            int lr = wm * WM + mf * 16 + (lane >> 2);
            sred[wn * 128 + lr] = part0;
            sred[wn * 128 + lr + 8] = part1;
        }
    }
    __syncthreads();
    {
        int r = row0 + tid;
        if (r < M) out[r] = sred[tid] + sred[128 + tid] + __ldg(bp2);
    }
}

// ---------------- predictor: build V rows = h[src]*h[dst], split to bf16 ----------------
__global__ void build_v_kernel(const float* __restrict__ h,
                               const int* __restrict__ psrc, const int* __restrict__ pdst,
                               const int* __restrict__ nsrc, const int* __restrict__ ndst,
                               __nv_bfloat16* __restrict__ Vh,
                               __nv_bfloat16* __restrict__ Vl, int P) {
    int idx = blockIdx.x * blockDim.x + threadIdx.x;
    int p = idx >> 5;
    if (p >= 2 * P) return;
    int c = (idx & 31) << 2;
    int s, d;
    if (p < P) { s = __ldg(psrc + p); d = __ldg(pdst + p); }
    else       { s = __ldg(nsrc + p - P); d = __ldg(ndst + p - P); }
    float4 a = *(const float4*)(h + (size_t)s * DH + c);
    float4 b = *(const float4*)(h + (size_t)d * DH + c);
    uint32_t h0, h1, l0, l1;
    split2(a.x * b.x, a.y * b.y, h0, l0);
    split2(a.z * b.z, a.w * b.w, h1, l1);
    size_t o = (size_t)p * DH + c;
    *(uint2*)(Vh + o) = make_uint2(h0, h1);
    *(uint2*)(Vl + o) = make_uint2(l0, l1);
}

// ---------------- launch ----------------
extern "C" void kernel_launch(void* const* d_in, const int* in_sizes, int n_in,
                              void* d_out, int out_size) {
    const float* x    = (const float*)d_in[0];
    const float* W1   = (const float*)d_in[1];
    const float* b1   = (const float*)d_in[2];
    const float* W2   = (const float*)d_in[3];
    const float* b2   = (const float*)d_in[4];
    const float* Wp1  = (const float*)d_in[5];
    const float* bp1  = (const float*)d_in[6];
    const float* Wp2  = (const float*)d_in[7];
    const float* bp2  = (const float*)d_in[8];
    const int*   esrc = (const int*)d_in[9];
    const int*   edst = (const int*)d_in[10];
    const int*   psrc = (const int*)d_in[11];
    const int*   pdst = (const int*)d_in[12];
    const int*   nsrc = (const int*)d_in[13];
    const int*   ndst = (const int*)d_in[14];
    float* out = (float*)d_out;

    float *hbuf, *z;
    __nv_bfloat16 *ah, *al, *w1h, *w1l, *w2h, *w2l, *wp1h, *wp1l;
    int *deg, *incl, *off, *cur, *bsum, *csr;
    cudaGetSymbolAddress((void**)&hbuf, g_h);
    cudaGetSymbolAddress((void**)&z,    g_z);
    cudaGetSymbolAddress((void**)&ah,   g_ah);
    cudaGetSymbolAddress((void**)&al,   g_al);
    cudaGetSymbolAddress((void**)&w1h,  g_w1h);
    cudaGetSymbolAddress((void**)&w1l,  g_w1l);
    cudaGetSymbolAddress((void**)&w2h,  g_w2h);
    cudaGetSymbolAddress((void**)&w2l,  g_w2l);
    cudaGetSymbolAddress((void**)&wp1h, g_wp1h);
    cudaGetSymbolAddress((void**)&wp1l, g_wp1l);
    cudaGetSymbolAddress((void**)&deg,  g_deg);
    cudaGetSymbolAddress((void**)&incl, g_incl);
    cudaGetSymbolAddress((void**)&off,  g_off);
    cudaGetSymbolAddress((void**)&cur,  g_cur);
    cudaGetSymbolAddress((void**)&bsum, g_bsum);
    cudaGetSymbolAddress((void**)&csr,  g_csr);

    __nv_bfloat16* zh = (__nv_bfloat16*)z;
    __nv_bfloat16* zl = zh + (size_t)NN * DMLP;
    __nv_bfloat16* vh = (__nv_bfloat16*)z;
    __nv_bfloat16* vl = vh + (size_t)2 * PP * DH;

    constexpr int SMEM_MAIN = 3 * 2 * (128 + 128) * 32 * 2;   // 96 KB
    constexpr int SMEM_PRED = 3 * 2 * (128 + 64) * 32 * 2;    // 72 KB
    cudaFuncSetAttribute(bf3_gemm<128, 128, 64, 32, 3, true>,
                         cudaFuncAttributeMaxDynamicSharedMemorySize, SMEM_MAIN);
    cudaFuncSetAttribute(bf3_gemm<128, 128, 64, 32, 3, false>,
                         cudaFuncAttributeMaxDynamicSharedMemorySize, SMEM_MAIN);
    cudaFuncSetAttribute(pred_gemm,
                         cudaFuncAttributeMaxDynamicSharedMemorySize, SMEM_PRED);

    float* out_h = out + 2 * PP;   // final h ([N,128]) lives in output

    // ---- fork: weight transposes on a side stream, CSR build on the main stream ----
    cudaStream_t s2;
    cudaStreamCreateWithFlags(&s2, cudaStreamNonBlocking);
    cudaEvent_t evFork, evJoin;
    cudaEventCreateWithFlags(&evFork, cudaEventDisableTiming);
    cudaEventCreateWithFlags(&evJoin, cudaEventDisableTiming);

    cudaEventRecord(evFork, 0);
    cudaStreamWaitEvent(s2, evFork, 0);
    transpose_split_kernel<<<dim3(DMLP / 32, DH / 32, LAYERS), dim3(32, 32), 0, s2>>>(
        W1, w1h, w1l, DH, DMLP);
    transpose_split_kernel<<<dim3(DH / 32, DMLP / 32, LAYERS), dim3(32, 32), 0, s2>>>(
        W2, w2h, w2l, DMLP, DH);
    transpose_split_kernel<<<dim3(DPRED / 32, DH / 32, 1), dim3(32, 32), 0, s2>>>(
        Wp1, wp1h, wp1l, DH, DPRED);
    cudaEventRecord(evJoin, s2);

    // ---- CSR build (main stream, parallel with transposes) ----
    zero_int_kernel<<<cdiv(NN, 256), 256>>>(deg, NN);
    hist_kernel<<<cdiv(EE, 256), 256>>>(edst, deg, EE);
    scan_block_kernel<<<SCAN_NB, SCAN_B>>>(deg, incl, bsum, NN);
    scan_sums_kernel<<<1, 128>>>(bsum, SCAN_NB);
    finalize_off_kernel<<<cdiv(NN, 256), 256>>>(incl, deg, bsum, off, cur, NN);
    fill_kernel<<<cdiv(EE, 256), 256>>>(esrc, edst, cur, csr, EE);

    cudaStreamWaitEvent(0, evJoin, 0);   // join before GEMMs consume weights

    const int M = NN;
    for (int l = 0; l < LAYERS; l++) {
        const float* hcur = (l == 0) ? x : hbuf;
        float* hnext = (l == LAYERS - 1) ? out_h : hbuf;

        gather_split_kernel<<<cdiv(NN * 32, 256), 256>>>(hcur, off, deg, csr, ah, al, NN);
        bf3_gemm<128, 128, 64, 32, 3, true>
            <<<dim3(cdiv(M, 128), DMLP / 128), 256, SMEM_MAIN>>>(
                ah, al, w1h + (size_t)l * DMLP * DH, w1l + (size_t)l * DMLP * DH,
                b1 + (size_t)l * DMLP, nullptr, zh, zl, M, DMLP, DH);
        bf3_gemm<128, 128, 64, 32, 3, false>
            <<<dim3(cdiv(M, 128), 1), 256, SMEM_MAIN>>>(
                zh, zl, w2h + (size_t)l * DH * DMLP, w2l + (size_t)l * DH * DMLP,
                b2 + (size_t)l * DH, hnext, nullptr, nullptr, M, DH, DMLP);
    }

    // ---- predictor: V build, then fused GEMM + matvec epilogue ----
    build_v_kernel<<<cdiv(2 * PP * 32, 256), 256>>>(out_h, psrc, pdst, nsrc, ndst, vh, vl, PP);
    pred_gemm<<<cdiv(2 * PP, 128), 128, SMEM_PRED>>>(
        vh, vl, wp1h, wp1l, bp1, Wp2, bp2, out, 2 * PP, DH);
}